// round 1
// baseline (speedup 1.0000x reference)
#include <cuda_runtime.h>

#define B_  2
#define S_  2048
#define D_  1024
#define H_  16
#define DK_ 64
#define M_  (B_*S_)   // 4096

// Scratch buffers (allocation-free rule: __device__ globals).
__device__ __align__(16) float g_q[B_*H_*S_*DK_];
__device__ __align__(16) float g_k[B_*H_*S_*DK_];
__device__ __align__(16) float g_v[B_*H_*S_*DK_];
__device__ __align__(16) float g_ao[M_*D_];

__device__ __forceinline__ float f2tf(float x) {
    unsigned int u = __float_as_uint(x), r;
    asm("cvt.rna.tf32.f32 %0, %1;" : "=r"(r) : "r"(u));
    return __uint_as_float(r);
}

__device__ __forceinline__ void mma8(float* d, const unsigned int* a, const unsigned int* b) {
    asm volatile(
        "mma.sync.aligned.m16n8k8.row.col.f32.tf32.tf32.f32 "
        "{%0,%1,%2,%3}, {%4,%5,%6,%7}, {%8,%9}, {%0,%1,%2,%3};\n"
        : "+f"(d[0]), "+f"(d[1]), "+f"(d[2]), "+f"(d[3])
        : "r"(a[0]), "r"(a[1]), "r"(a[2]), "r"(a[3]),
          "r"(b[0]), "r"(b[1]));
}

// ---------------------------------------------------------------------------
// GEMM: out[m][n] = sum_k A[m][k] * W[n][k]   (M=4096, N=1024, K=1024)
// mode 0: plain write to out[m*D_+n]                     (final projection)
// mode 1: RoPE rotate, write [b][h][s][dk] layout        (Q)
// mode 2: RoPE rotate, write [b][h][s][dk] layout        (K)
// mode 3: plain, write [b][h][s][dk] layout              (V)
// ---------------------------------------------------------------------------
#define GBM 128
#define GBN 64
#define GBK 32

__device__ __forceinline__ void store_pair(
    int mode, float* __restrict__ out,
    const float* __restrict__ cosT, const float* __restrict__ sinT,
    int r, int c, float v0, float v1)
{
    if (mode == 0) {
        out[r*D_ + c]     = v0;
        out[r*D_ + c + 1] = v1;
        return;
    }
    int s = r & (S_-1), b = r >> 11;
    int h = c >> 6, dk = c & 63;
    int idx = (((b*H_ + h)*S_) + s)*DK_ + dk;
    if (mode == 3) {
        out[idx]     = v0;
        out[idx + 1] = v1;
        return;
    }
    float cs = cosT[s*(DK_/2) + (dk >> 1)];
    float sn = sinT[s*(DK_/2) + (dk >> 1)];
    out[idx]     = v0*cs - v1*sn;
    out[idx + 1] = v0*sn + v1*cs;
}

__global__ void __launch_bounds__(256)
gemm_kernel(const float* __restrict__ A, const float* __restrict__ W,
            float* __restrict__ out,
            const float* __restrict__ cosT, const float* __restrict__ sinT,
            int mode)
{
    __shared__ float As[GBM][GBK+1];
    __shared__ float Bs[GBN][GBK+1];

    int tid  = threadIdx.x;
    int lane = tid & 31, wid = tid >> 5;
    int g = lane >> 2, tg = lane & 3;
    int wm = (wid & 3) * 32, wn = (wid >> 2) * 32;
    int m0 = blockIdx.y * GBM, n0 = blockIdx.x * GBN;

    float acc[2][4][4];
    #pragma unroll
    for (int i = 0; i < 2; i++)
        #pragma unroll
        for (int j = 0; j < 4; j++)
            #pragma unroll
            for (int e = 0; e < 4; e++) acc[i][j][e] = 0.f;

    for (int kb = 0; kb < D_; kb += GBK) {
        // A tile 128x32 (float4 gmem loads, scalar tf32-rounded smem stores)
        #pragma unroll
        for (int it = 0; it < 4; it++) {
            int idx = tid + it*256;
            int r = idx >> 3, c = (idx & 7) * 4;
            float4 v = *(const float4*)(A + (m0 + r)*D_ + kb + c);
            As[r][c]   = f2tf(v.x);
            As[r][c+1] = f2tf(v.y);
            As[r][c+2] = f2tf(v.z);
            As[r][c+3] = f2tf(v.w);
        }
        // B tile 64x32 (W rows are K-major -> col-major B operand)
        #pragma unroll
        for (int it = 0; it < 2; it++) {
            int idx = tid + it*256;
            int r = idx >> 3, c = (idx & 7) * 4;
            float4 v = *(const float4*)(W + (n0 + r)*D_ + kb + c);
            Bs[r][c]   = f2tf(v.x);
            Bs[r][c+1] = f2tf(v.y);
            Bs[r][c+2] = f2tf(v.z);
            Bs[r][c+3] = f2tf(v.w);
        }
        __syncthreads();

        #pragma unroll
        for (int ks = 0; ks < 4; ks++) {
            int k8 = ks * 8;
            unsigned int af[2][4], bf[4][2];
            #pragma unroll
            for (int mi = 0; mi < 2; mi++) {
                int r = wm + mi*16 + g;
                af[mi][0] = __float_as_uint(As[r  ][k8+tg]);
                af[mi][1] = __float_as_uint(As[r+8][k8+tg]);
                af[mi][2] = __float_as_uint(As[r  ][k8+tg+4]);
                af[mi][3] = __float_as_uint(As[r+8][k8+tg+4]);
            }
            #pragma unroll
            for (int ni = 0; ni < 4; ni++) {
                int c = wn + ni*8 + g;
                bf[ni][0] = __float_as_uint(Bs[c][k8+tg]);
                bf[ni][1] = __float_as_uint(Bs[c][k8+tg+4]);
            }
            #pragma unroll
            for (int mi = 0; mi < 2; mi++)
                #pragma unroll
                for (int ni = 0; ni < 4; ni++)
                    mma8(acc[mi][ni], af[mi], bf[ni]);
        }
        __syncthreads();
    }

    #pragma unroll
    for (int mi = 0; mi < 2; mi++) {
        #pragma unroll
        for (int ni = 0; ni < 4; ni++) {
            int r = m0 + wm + mi*16 + g;
            int c = n0 + wn + ni*8 + 2*tg;
            store_pair(mode, out, cosT, sinT, r,     c, acc[mi][ni][0], acc[mi][ni][1]);
            store_pair(mode, out, cosT, sinT, r + 8, c, acc[mi][ni][2], acc[mi][ni][3]);
        }
    }
}

// ---------------------------------------------------------------------------
// Flash attention: 1 block = 64 q-rows of one (b,h). 128 threads / 4 warps.
// Each warp owns 16 q-rows -> row reductions stay within a thread-quad.
// logits = (q.k)/64 with causal mask (-1e9).
// ---------------------------------------------------------------------------
#define LDS_ 65
#define ATTN_SMEM (4*64*LDS_*(int)sizeof(float))

__global__ void __launch_bounds__(128)
attn_kernel()
{
    extern __shared__ float sm[];
    float* Qs = sm;
    float* Ks = sm + 64*LDS_;
    float* Vs = sm + 2*64*LDS_;
    float* Ps = sm + 3*64*LDS_;

    int qt = blockIdx.x;
    int bh = blockIdx.y;
    int b = bh >> 4, h = bh & 15;
    int tid = threadIdx.x, lane = tid & 31, w = tid >> 5;
    int g = lane >> 2, tg = lane & 3;

    const float* qp = g_q + (size_t)bh * S_ * DK_;
    const float* kp = g_k + (size_t)bh * S_ * DK_;
    const float* vp = g_v + (size_t)bh * S_ * DK_;

    // Q tile (persistent in smem)
    #pragma unroll
    for (int it = 0; it < 8; it++) {
        int idx = tid + it*128;
        int r = idx >> 4, c = (idx & 15) * 4;
        float4 v4 = *(const float4*)(qp + (qt*64 + r)*DK_ + c);
        Qs[r*LDS_+c]   = f2tf(v4.x);
        Qs[r*LDS_+c+1] = f2tf(v4.y);
        Qs[r*LDS_+c+2] = f2tf(v4.z);
        Qs[r*LDS_+c+3] = f2tf(v4.w);
    }

    float oacc[8][4];
    #pragma unroll
    for (int ni = 0; ni < 8; ni++)
        #pragma unroll
        for (int e = 0; e < 4; e++) oacc[ni][e] = 0.f;

    float mA = -1e30f, mB = -1e30f, lA = 0.f, lB = 0.f;
    const float scale = 1.0f / 64.0f;

    for (int kt = 0; kt <= qt; kt++) {
        __syncthreads();   // guard Ks/Vs reuse (and Q store on first iter)
        #pragma unroll
        for (int it = 0; it < 8; it++) {
            int idx = tid + it*128;
            int r = idx >> 4, c = (idx & 15) * 4;
            float4 kv = *(const float4*)(kp + (kt*64 + r)*DK_ + c);
            Ks[r*LDS_+c]   = f2tf(kv.x);
            Ks[r*LDS_+c+1] = f2tf(kv.y);
            Ks[r*LDS_+c+2] = f2tf(kv.z);
            Ks[r*LDS_+c+3] = f2tf(kv.w);
            float4 vv = *(const float4*)(vp + (kt*64 + r)*DK_ + c);
            Vs[r*LDS_+c]   = f2tf(vv.x);
            Vs[r*LDS_+c+1] = f2tf(vv.y);
            Vs[r*LDS_+c+2] = f2tf(vv.z);
            Vs[r*LDS_+c+3] = f2tf(vv.w);
        }
        __syncthreads();

        // S = Q K^T over dk=64 (8 k8-steps); warp computes 16x64
        float sacc[8][4];
        #pragma unroll
        for (int ni = 0; ni < 8; ni++)
            #pragma unroll
            for (int e = 0; e < 4; e++) sacc[ni][e] = 0.f;

        #pragma unroll
        for (int ks = 0; ks < 8; ks++) {
            int k8 = ks * 8;
            unsigned int af[4];
            int r = w*16 + g;
            af[0] = __float_as_uint(Qs[ r   *LDS_ + k8+tg]);
            af[1] = __float_as_uint(Qs[(r+8)*LDS_ + k8+tg]);
            af[2] = __float_as_uint(Qs[ r   *LDS_ + k8+tg+4]);
            af[3] = __float_as_uint(Qs[(r+8)*LDS_ + k8+tg+4]);
            #pragma unroll
            for (int ni = 0; ni < 8; ni++) {
                unsigned int bf[2];
                bf[0] = __float_as_uint(Ks[(ni*8+g)*LDS_ + k8+tg]);
                bf[1] = __float_as_uint(Ks[(ni*8+g)*LDS_ + k8+tg+4]);
                mma8(sacc[ni], af, bf);
            }
        }

        // scale + causal mask
        int rowA = qt*64 + w*16 + g;
        int rowB = rowA + 8;
        float tmA = -1e30f, tmB = -1e30f;
        #pragma unroll
        for (int ni = 0; ni < 8; ni++) {
            int colBase = kt*64 + ni*8 + 2*tg;
            float v0 = sacc[ni][0]*scale, v1 = sacc[ni][1]*scale;
            float v2 = sacc[ni][2]*scale, v3 = sacc[ni][3]*scale;
            if (colBase     > rowA) v0 = -1e9f;
            if (colBase + 1 > rowA) v1 = -1e9f;
            if (colBase     > rowB) v2 = -1e9f;
            if (colBase + 1 > rowB) v3 = -1e9f;
            sacc[ni][0] = v0; sacc[ni][1] = v1;
            sacc[ni][2] = v2; sacc[ni][3] = v3;
            tmA = fmaxf(tmA, fmaxf(v0, v1));
            tmB = fmaxf(tmB, fmaxf(v2, v3));
        }
        tmA = fmaxf(tmA, __shfl_xor_sync(0xffffffffu, tmA, 1));
        tmA = fmaxf(tmA, __shfl_xor_sync(0xffffffffu, tmA, 2));
        tmB = fmaxf(tmB, __shfl_xor_sync(0xffffffffu, tmB, 1));
        tmB = fmaxf(tmB, __shfl_xor_sync(0xffffffffu, tmB, 2));

        float mAn = fmaxf(mA, tmA), mBn = fmaxf(mB, tmB);
        float alA = __expf(mA - mAn), alB = __expf(mB - mBn);

        float sumA = 0.f, sumB = 0.f;
        int rA = w*16 + g, rB = rA + 8;
        #pragma unroll
        for (int ni = 0; ni < 8; ni++) {
            float p0 = __expf(sacc[ni][0] - mAn);
            float p1 = __expf(sacc[ni][1] - mAn);
            float p2 = __expf(sacc[ni][2] - mBn);
            float p3 = __expf(sacc[ni][3] - mBn);
            sumA += p0 + p1;
            sumB += p2 + p3;
            int c0 = ni*8 + 2*tg;
            Ps[rA*LDS_ + c0]     = f2tf(p0);
            Ps[rA*LDS_ + c0 + 1] = f2tf(p1);
            Ps[rB*LDS_ + c0]     = f2tf(p2);
            Ps[rB*LDS_ + c0 + 1] = f2tf(p3);
        }
        sumA += __shfl_xor_sync(0xffffffffu, sumA, 1);
        sumA += __shfl_xor_sync(0xffffffffu, sumA, 2);
        sumB += __shfl_xor_sync(0xffffffffu, sumB, 1);
        sumB += __shfl_xor_sync(0xffffffffu, sumB, 2);

        lA = lA * alA + sumA;
        lB = lB * alB + sumB;
        mA = mAn; mB = mBn;

        #pragma unroll
        for (int ni = 0; ni < 8; ni++) {
            oacc[ni][0] *= alA; oacc[ni][1] *= alA;
            oacc[ni][2] *= alB; oacc[ni][3] *= alB;
        }

        __syncwarp();   // Ps cross-lane visibility (warp-private rows)

        // O += P V  (k dim = 64 keys)
        #pragma unroll
        for (int ks = 0; ks < 8; ks++) {
            int k8 = ks * 8;
            unsigned int af[4];
            af[0] = __float_as_uint(Ps[ rA   *LDS_ + k8+tg]);
            af[1] = __float_as_uint(Ps[(rA+8)*LDS_ + k8+tg]);
            af[2] = __float_as_uint(Ps[ rA   *LDS_ + k8+tg+4]);
            af[3] = __float_as_uint(Ps[(rA+8)*LDS_ + k8+tg+4]);
            #pragma unroll
            for (int ni = 0; ni < 8; ni++) {
                unsigned int bf[2];
                bf[0] = __float_as_uint(Vs[(k8+tg  )*LDS_ + ni*8+g]);
                bf[1] = __float_as_uint(Vs[(k8+tg+4)*LDS_ + ni*8+g]);
                mma8(oacc[ni], af, bf);
            }
        }
    }

    float invA = 1.f / lA, invB = 1.f / lB;
    int sA = qt*64 + w*16 + g;
    int sB = sA + 8;
    float* aoA = g_ao + ((size_t)b*S_ + sA)*D_ + h*DK_;
    float* aoB = g_ao + ((size_t)b*S_ + sB)*D_ + h*DK_;
    #pragma unroll
    for (int ni = 0; ni < 8; ni++) {
        int c = ni*8 + 2*tg;
        aoA[c]     = oacc[ni][0] * invA;
        aoA[c + 1] = oacc[ni][1] * invA;
        aoB[c]     = oacc[ni][2] * invB;
        aoB[c + 1] = oacc[ni][3] * invB;
    }
}

// ---------------------------------------------------------------------------

extern "C" void kernel_launch(void* const* d_in, const int* in_sizes, int n_in,
                              void* d_out, int out_size)
{
    const float* x  = (const float*)d_in[0];
    const float* fc = (const float*)d_in[1];
    const float* fs = (const float*)d_in[2];
    // d_in[3] is the additive mask; causality is applied analytically.
    const float* wq = (const float*)d_in[4];
    const float* wk = (const float*)d_in[5];
    const float* wv = (const float*)d_in[6];
    const float* wo = (const float*)d_in[7];
    float* out = (float*)d_out;

    float *qb, *kb, *vb, *ab;
    cudaGetSymbolAddress((void**)&qb, g_q);
    cudaGetSymbolAddress((void**)&kb, g_k);
    cudaGetSymbolAddress((void**)&vb, g_v);
    cudaGetSymbolAddress((void**)&ab, g_ao);

    dim3 gg(D_/GBN, M_/GBM);   // (16, 32)
    gemm_kernel<<<gg, 256>>>(x, wq, qb, fc, fs, 1);
    gemm_kernel<<<gg, 256>>>(x, wk, kb, fc, fs, 2);
    gemm_kernel<<<gg, 256>>>(x, wv, vb, fc, fs, 3);

    cudaFuncSetAttribute(attn_kernel,
                         cudaFuncAttributeMaxDynamicSharedMemorySize, ATTN_SMEM);
    attn_kernel<<<dim3(S_/64, B_*H_), 128, ATTN_SMEM>>>();

    gemm_kernel<<<gg, 256>>>(ab, wo, out, fc, fs, 0);
}

// round 3
// speedup vs baseline: 1.1372x; 1.1372x over previous
#include <cuda_runtime.h>

#define B_  2
#define S_  2048
#define D_  1024
#define H_  16
#define DK_ 64
#define M_  (B_*S_)   // 4096

// Scratch buffers (allocation-free rule: __device__ globals).
__device__ __align__(16) float g_q[B_*H_*S_*DK_];
__device__ __align__(16) float g_k[B_*H_*S_*DK_];
__device__ __align__(16) float g_v[B_*H_*S_*DK_];
__device__ __align__(16) float g_ao[M_*D_];

__device__ __forceinline__ float f2tf(float x) {
    unsigned int u = __float_as_uint(x), r;
    asm("cvt.rna.tf32.f32 %0, %1;" : "=r"(r) : "r"(u));
    return __uint_as_float(r);
}

__device__ __forceinline__ void mma8(float* d, const unsigned int* a, const unsigned int* b) {
    asm volatile(
        "mma.sync.aligned.m16n8k8.row.col.f32.tf32.tf32.f32 "
        "{%0,%1,%2,%3}, {%4,%5,%6,%7}, {%8,%9}, {%0,%1,%2,%3};\n"
        : "+f"(d[0]), "+f"(d[1]), "+f"(d[2]), "+f"(d[3])
        : "r"(a[0]), "r"(a[1]), "r"(a[2]), "r"(a[3]),
          "r"(b[0]), "r"(b[1]));
}

// ---------------------------------------------------------------------------
// GEMM: out[m][n] = sum_k A[m][k] * W[n][k]   (M=4096, N=1024, K=1024)
// No smem: fragments gathered directly from gmem (L1/L2 cached), tf32 mma.
// Block 128x128, 8 warps, warp tile 64x32 (4 mi x 4 ni).
// mode 0: plain row-major out ; mode 1: RoPE -> [b][h][s][dk] ; mode 3: plain -> [b][h][s][dk]
// ---------------------------------------------------------------------------
__device__ __forceinline__ void store_pair(
    int mode, float* __restrict__ out,
    const float* __restrict__ cosT, const float* __restrict__ sinT,
    int r, int c, float v0, float v1)
{
    if (mode == 0) {
        float2 p = make_float2(v0, v1);
        *(float2*)(out + (size_t)r*D_ + c) = p;
        return;
    }
    int s = r & (S_-1), b = r >> 11;
    int h = c >> 6, dk = c & 63;
    size_t idx = (((size_t)(b*H_ + h)*S_) + s)*DK_ + dk;
    if (mode == 3) {
        float2 p = make_float2(v0, v1);
        *(float2*)(out + idx) = p;
        return;
    }
    float cs = cosT[s*(DK_/2) + (dk >> 1)];
    float sn = sinT[s*(DK_/2) + (dk >> 1)];
    float2 p = make_float2(v0*cs - v1*sn, v0*sn + v1*cs);
    *(float2*)(out + idx) = p;
}

__global__ void __launch_bounds__(256)
gemm_kernel(const float* __restrict__ A,
            const float* __restrict__ Wq, const float* __restrict__ Wk,
            const float* __restrict__ Wv,
            float* __restrict__ Oq, float* __restrict__ Ok, float* __restrict__ Ov,
            const float* __restrict__ cosT, const float* __restrict__ sinT,
            int fused)
{
    const float* __restrict__ W;
    float* __restrict__ out;
    int mode;
    if (fused) {
        int z = blockIdx.z;
        W   = (z == 0) ? Wq : (z == 1) ? Wk : Wv;
        out = (z == 0) ? Oq : (z == 1) ? Ok : Ov;
        mode = (z == 2) ? 3 : 1;
    } else { W = Wq; out = Oq; mode = 0; }

    int tid = threadIdx.x, lane = tid & 31, wid = tid >> 5;
    int g = lane >> 2, tg = lane & 3;
    int wrow = wid >> 2, wcol = wid & 3;           // 2 x 4 warp grid
    int m0 = blockIdx.y * 128, n0 = blockIdx.x * 128;

    const float* ap[8];
    #pragma unroll
    for (int mi = 0; mi < 4; mi++) {
        int r = m0 + wrow*64 + mi*16 + g;
        ap[mi*2]   = A + (size_t)r*D_ + tg;
        ap[mi*2+1] = A + (size_t)(r+8)*D_ + tg;
    }
    const float* bp[4];
    #pragma unroll
    for (int ni = 0; ni < 4; ni++) {
        int c = n0 + wcol*32 + ni*8 + g;
        bp[ni] = W + (size_t)c*D_ + tg;
    }

    float acc[4][4][4];
    #pragma unroll
    for (int mi = 0; mi < 4; mi++)
        #pragma unroll
        for (int ni = 0; ni < 4; ni++)
            #pragma unroll
            for (int e = 0; e < 4; e++) acc[mi][ni][e] = 0.f;

    #pragma unroll 2
    for (int k8 = 0; k8 < D_; k8 += 8) {
        unsigned int af[4][4], bf[4][2];
        #pragma unroll
        for (int mi = 0; mi < 4; mi++) {
            af[mi][0] = __float_as_uint(f2tf(ap[mi*2  ][k8]));
            af[mi][1] = __float_as_uint(f2tf(ap[mi*2+1][k8]));
            af[mi][2] = __float_as_uint(f2tf(ap[mi*2  ][k8+4]));
            af[mi][3] = __float_as_uint(f2tf(ap[mi*2+1][k8+4]));
        }
        #pragma unroll
        for (int ni = 0; ni < 4; ni++) {
            bf[ni][0] = __float_as_uint(f2tf(bp[ni][k8]));
            bf[ni][1] = __float_as_uint(f2tf(bp[ni][k8+4]));
        }
        #pragma unroll
        for (int mi = 0; mi < 4; mi++)
            #pragma unroll
            for (int ni = 0; ni < 4; ni++)
                mma8(acc[mi][ni], af[mi], bf[ni]);
    }

    #pragma unroll
    for (int mi = 0; mi < 4; mi++) {
        #pragma unroll
        for (int ni = 0; ni < 4; ni++) {
            int r = m0 + wrow*64 + mi*16 + g;
            int c = n0 + wcol*32 + ni*8 + 2*tg;
            store_pair(mode, out, cosT, sinT, r,     c, acc[mi][ni][0], acc[mi][ni][1]);
            store_pair(mode, out, cosT, sinT, r + 8, c, acc[mi][ni][2], acc[mi][ni][3]);
        }
    }
}

// ---------------------------------------------------------------------------
// Flash attention v2: 1 block = 128 q-rows of one (b,h), 8 warps x 16 rows.
// Q fragments in registers (pre-scaled by 1/64). K and V^T in smem with
// pair-interleaved columns so every b-fragment is one conflict-free LDS.64.
// P is re-fragmented via warp shuffles (no smem round trip).
// ---------------------------------------------------------------------------
#define KSTR 72   // smem row stride (floats): conflict-free for interleaved LDS.64

__global__ void __launch_bounds__(256, 2)
attn_kernel()
{
    __shared__ float Ks[64 * KSTR];
    __shared__ float Vt[64 * KSTR];

    int qt = blockIdx.x;          // 0..15  (128-row q tile)
    int bh = blockIdx.y;          // 0..31
    int b = bh >> 4, h = bh & 15;
    int tid = threadIdx.x, lane = tid & 31, w = tid >> 5;
    int g = lane >> 2, tg = lane & 3;

    const float* qp = g_q + (size_t)bh * S_ * DK_;
    const float* kp = g_k + (size_t)bh * S_ * DK_;
    const float* vp = g_v + (size_t)bh * S_ * DK_;

    int rowA = qt*128 + w*16 + g;   // global q row (lane's row A)
    int rowB = rowA + 8;
    int rowmax = qt*128 + w*16 + 15;

    // Q fragments, pre-scaled by 1/64 (folds the double 1/sqrt(dk))
    unsigned int aq[8][4];
    #pragma unroll
    for (int ks = 0; ks < 8; ks++) {
        int k8 = ks * 8;
        aq[ks][0] = __float_as_uint(f2tf(qp[(size_t)rowA*DK_ + k8+tg  ] * 0.015625f));
        aq[ks][1] = __float_as_uint(f2tf(qp[(size_t)rowB*DK_ + k8+tg  ] * 0.015625f));
        aq[ks][2] = __float_as_uint(f2tf(qp[(size_t)rowA*DK_ + k8+tg+4] * 0.015625f));
        aq[ks][3] = __float_as_uint(f2tf(qp[(size_t)rowB*DK_ + k8+tg+4] * 0.015625f));
    }

    float oacc[8][4];
    #pragma unroll
    for (int ni = 0; ni < 8; ni++)
        #pragma unroll
        for (int e = 0; e < 4; e++) oacc[ni][e] = 0.f;

    float mA = -1e30f, mB = -1e30f, lA = 0.f, lB = 0.f;

    int ntiles = 2*qt + 2;
    for (int kt = 0; kt < ntiles; kt++) {
        int kb = kt * 64;
        __syncthreads();
        // K fill: row-major, columns pair-interleaved [0,4,1,5,2,6,3,7] per 8-group
        #pragma unroll
        for (int it = 0; it < 4; it++) {
            int idx = tid + it*256;
            int r = idx >> 4, c = (idx & 15) * 4;
            float4 v4 = *(const float4*)(kp + (size_t)(kb + r)*DK_ + c);
            int base = r*KSTR + (c & ~7) + ((c & 4) ? 1 : 0);
            Ks[base    ] = f2tf(v4.x);
            Ks[base + 2] = f2tf(v4.y);
            Ks[base + 4] = f2tf(v4.z);
            Ks[base + 6] = f2tf(v4.w);
        }
        // V fill transposed: Vt[dk][perm(key)], same pair interleave on key index
        #pragma unroll
        for (int it = 0; it < 4; it++) {
            int idx = tid + it*256;
            int r = idx & 63, c = (idx >> 6) * 4;
            float4 v4 = *(const float4*)(vp + (size_t)(kb + r)*DK_ + c);
            int pr = (r & ~7) + ((r & 3)*2) + ((r >> 2) & 1);
            Vt[(c    )*KSTR + pr] = f2tf(v4.x);
            Vt[(c + 1)*KSTR + pr] = f2tf(v4.y);
            Vt[(c + 2)*KSTR + pr] = f2tf(v4.z);
            Vt[(c + 3)*KSTR + pr] = f2tf(v4.w);
        }
        __syncthreads();

        if (kb > rowmax) continue;   // fully masked for this warp

        // S = (Q/64) K^T  : warp computes 16 x 64
        float sacc[8][4];
        #pragma unroll
        for (int ni = 0; ni < 8; ni++)
            #pragma unroll
            for (int e = 0; e < 4; e++) sacc[ni][e] = 0.f;

        #pragma unroll
        for (int ks = 0; ks < 8; ks++) {
            #pragma unroll
            for (int ni = 0; ni < 8; ni++) {
                float2 bv = *(const float2*)(&Ks[(ni*8 + g)*KSTR + ks*8 + 2*tg]);
                unsigned int bf[2] = { __float_as_uint(bv.x), __float_as_uint(bv.y) };
                mma8(sacc[ni], aq[ks], bf);
            }
        }

        // causal mask + running row max
        float tmA = -1e30f, tmB = -1e30f;
        #pragma unroll
        for (int ni = 0; ni < 8; ni++) {
            int c0 = kb + ni*8 + 2*tg;
            float v0 = sacc[ni][0], v1 = sacc[ni][1];
            float v2 = sacc[ni][2], v3 = sacc[ni][3];
            if (c0     > rowA) v0 = -1e9f;
            if (c0 + 1 > rowA) v1 = -1e9f;
            if (c0     > rowB) v2 = -1e9f;
            if (c0 + 1 > rowB) v3 = -1e9f;
            sacc[ni][0] = v0; sacc[ni][1] = v1;
            sacc[ni][2] = v2; sacc[ni][3] = v3;
            tmA = fmaxf(tmA, fmaxf(v0, v1));
            tmB = fmaxf(tmB, fmaxf(v2, v3));
        }
        tmA = fmaxf(tmA, __shfl_xor_sync(0xffffffffu, tmA, 1));
        tmA = fmaxf(tmA, __shfl_xor_sync(0xffffffffu, tmA, 2));
        tmB = fmaxf(tmB, __shfl_xor_sync(0xffffffffu, tmB, 1));
        tmB = fmaxf(tmB, __shfl_xor_sync(0xffffffffu, tmB, 2));

        float mAn = fmaxf(mA, tmA), mBn = fmaxf(mB, tmB);
        float alA = __expf(mA - mAn), alB = __expf(mB - mBn);

        float sumA = 0.f, sumB = 0.f;
        #pragma unroll
        for (int ni = 0; ni < 8; ni++) {
            float p0 = __expf(sacc[ni][0] - mAn);
            float p1 = __expf(sacc[ni][1] - mAn);
            float p2 = __expf(sacc[ni][2] - mBn);
            float p3 = __expf(sacc[ni][3] - mBn);
            sumA += p0 + p1;
            sumB += p2 + p3;
            sacc[ni][0] = f2tf(p0); sacc[ni][1] = f2tf(p1);
            sacc[ni][2] = f2tf(p2); sacc[ni][3] = f2tf(p3);
        }
        sumA += __shfl_xor_sync(0xffffffffu, sumA, 1);
        sumA += __shfl_xor_sync(0xffffffffu, sumA, 2);
        sumB += __shfl_xor_sync(0xffffffffu, sumB, 1);
        sumB += __shfl_xor_sync(0xffffffffu, sumB, 2);

        lA = lA * alA + sumA;
        lB = lB * alB + sumB;
        mA = mAn; mB = mBn;

        #pragma unroll
        for (int ni = 0; ni < 8; ni++) {
            oacc[ni][0] *= alA; oacc[ni][1] *= alA;
            oacc[ni][2] *= alB; oacc[ni][3] *= alB;
        }

        // O += P V : P a-fragments built from c-fragments via shuffles
        int srcA = (lane & ~3) | (tg >> 1);
        int srcB = srcA + 2;
        bool odd = (tg & 1);
        #pragma unroll
        for (int ks = 0; ks < 8; ks++) {
            float x0 = __shfl_sync(0xffffffffu, sacc[ks][0], srcA);
            float y0 = __shfl_sync(0xffffffffu, sacc[ks][1], srcA);
            float x1 = __shfl_sync(0xffffffffu, sacc[ks][2], srcA);
            float y1 = __shfl_sync(0xffffffffu, sacc[ks][3], srcA);
            float x2 = __shfl_sync(0xffffffffu, sacc[ks][0], srcB);
            float y2 = __shfl_sync(0xffffffffu, sacc[ks][1], srcB);
            float x3 = __shfl_sync(0xffffffffu, sacc[ks][2], srcB);
            float y3 = __shfl_sync(0xffffffffu, sacc[ks][3], srcB);
            unsigned int af[4];
            af[0] = __float_as_uint(odd ? y0 : x0);
            af[1] = __float_as_uint(odd ? y1 : x1);
            af[2] = __float_as_uint(odd ? y2 : x2);
            af[3] = __float_as_uint(odd ? y3 : x3);
            #pragma unroll
            for (int ni = 0; ni < 8; ni++) {
                float2 bv = *(const float2*)(&Vt[(ni*8 + g)*KSTR + ks*8 + 2*tg]);
                unsigned int bf[2] = { __float_as_uint(bv.x), __float_as_uint(bv.y) };
                mma8(oacc[ni], af, bf);
            }
        }
    }

    float invA = 1.f / lA, invB = 1.f / lB;
    float* aoA = g_ao + ((size_t)b*S_ + rowA)*D_ + h*DK_;
    float* aoB = aoA + (size_t)8*D_;
    #pragma unroll
    for (int ni = 0; ni < 8; ni++) {
        int c = ni*8 + 2*tg;
        float2 pa = make_float2(oacc[ni][0]*invA, oacc[ni][1]*invA);
        float2 pb = make_float2(oacc[ni][2]*invB, oacc[ni][3]*invB);
        *(float2*)(aoA + c) = pa;
        *(float2*)(aoB + c) = pb;
    }
}

// ---------------------------------------------------------------------------

extern "C" void kernel_launch(void* const* d_in, const int* in_sizes, int n_in,
                              void* d_out, int out_size)
{
    const float* x  = (const float*)d_in[0];
    const float* fc = (const float*)d_in[1];
    const float* fs = (const float*)d_in[2];
    // d_in[3] is the additive mask; causality is applied analytically.
    const float* wq = (const float*)d_in[4];
    const float* wk = (const float*)d_in[5];
    const float* wv = (const float*)d_in[6];
    const float* wo = (const float*)d_in[7];
    float* out = (float*)d_out;

    float *qb, *kb, *vb, *ab;
    cudaGetSymbolAddress((void**)&qb, g_q);
    cudaGetSymbolAddress((void**)&kb, g_k);
    cudaGetSymbolAddress((void**)&vb, g_v);
    cudaGetSymbolAddress((void**)&ab, g_ao);

    // Fused QKV projections (+RoPE on Q,K) in one launch
    gemm_kernel<<<dim3(D_/128, M_/128, 3), 256>>>(x, wq, wk, wv, qb, kb, vb, fc, fs, 1);

    attn_kernel<<<dim3(S_/128, B_*H_), 256>>>();

    // Output projection
    gemm_kernel<<<dim3(D_/128, M_/128, 1), 256>>>(ab, wo, 0, 0, out, 0, 0, fc, fs, 0);
}

// round 4
// speedup vs baseline: 1.9655x; 1.7283x over previous
#include <cuda_runtime.h>

#define B_  2
#define S_  2048
#define D_  1024
#define H_  16
#define DK_ 64
#define M_  (B_*S_)   // 4096

// Scratch buffers (allocation-free rule: __device__ globals).
__device__ __align__(16) float g_q[B_*H_*S_*DK_];
__device__ __align__(16) float g_k[B_*H_*S_*DK_];
__device__ __align__(16) float g_v[B_*H_*S_*DK_];
__device__ __align__(16) float g_ao[M_*D_];

__device__ __forceinline__ float f2tf(float x) {
    unsigned int u = __float_as_uint(x), r;
    asm("cvt.rna.tf32.f32 %0, %1;" : "=r"(r) : "r"(u));
    return __uint_as_float(r);
}

__device__ __forceinline__ void mma8(float* d, const unsigned int* a, const unsigned int* b) {
    asm volatile(
        "mma.sync.aligned.m16n8k8.row.col.f32.tf32.tf32.f32 "
        "{%0,%1,%2,%3}, {%4,%5,%6,%7}, {%8,%9}, {%0,%1,%2,%3};\n"
        : "+f"(d[0]), "+f"(d[1]), "+f"(d[2]), "+f"(d[3])
        : "r"(a[0]), "r"(a[1]), "r"(a[2]), "r"(a[3]),
          "r"(b[0]), "r"(b[1]));
}

// ---------------------------------------------------------------------------
// GEMM: out[m][n] = sum_k A[m][k] * W[n][k]   (M=4096, N=1024, K=1024)
// Double-buffered smem, k-pair-interleaved layout (stride 24 floats) so each
// B-fragment is one conflict-free LDS.64 and each A-fragment is two.
// Block 128x128, 8 warps (2x4), warp tile 64x32, K-tile 16.
// mode 0: row-major out ; mode 1: RoPE -> [b][h][s][dk] ; mode 3: -> [b][h][s][dk]
// ---------------------------------------------------------------------------
#define GSTR 24   // smem row stride (floats); 96B row ≡ 32B mod 128 -> conflict-free LDS.64

__device__ __forceinline__ void store_pair(
    int mode, float* __restrict__ out,
    const float* __restrict__ cosT, const float* __restrict__ sinT,
    int r, int c, float v0, float v1)
{
    if (mode == 0) {
        *(float2*)(out + (size_t)r*D_ + c) = make_float2(v0, v1);
        return;
    }
    int s = r & (S_-1), b = r >> 11;
    int h = c >> 6, dk = c & 63;
    size_t idx = (((size_t)(b*H_ + h)*S_) + s)*DK_ + dk;
    if (mode == 3) {
        *(float2*)(out + idx) = make_float2(v0, v1);
        return;
    }
    float cs = cosT[s*(DK_/2) + (dk >> 1)];
    float sn = sinT[s*(DK_/2) + (dk >> 1)];
    *(float2*)(out + idx) = make_float2(v0*cs - v1*sn, v0*sn + v1*cs);
}

__global__ void __launch_bounds__(256)
gemm_kernel(const float* __restrict__ A,
            const float* __restrict__ Wq, const float* __restrict__ Wk,
            const float* __restrict__ Wv,
            float* __restrict__ Oq, float* __restrict__ Ok, float* __restrict__ Ov,
            const float* __restrict__ cosT, const float* __restrict__ sinT,
            int fused)
{
    __shared__ float As[2][128*GSTR];
    __shared__ float Bs[2][128*GSTR];

    const float* __restrict__ W;
    float* __restrict__ out;
    int mode;
    if (fused) {
        int z = blockIdx.z;
        W   = (z == 0) ? Wq : (z == 1) ? Wk : Wv;
        out = (z == 0) ? Oq : (z == 1) ? Ok : Ov;
        mode = (z == 2) ? 3 : 1;
    } else { W = Wq; out = Oq; mode = 0; }

    int tid = threadIdx.x, lane = tid & 31, wid = tid >> 5;
    int g = lane >> 2, tg = lane & 3;
    int wrow = wid >> 2, wcol = wid & 3;           // 2 x 4 warp grid
    int m0 = blockIdx.y * 128, n0 = blockIdx.x * 128;

    // Fill mapping: thread covers rows fr, fr+64 with one float4 (k-span 4) each.
    int fr = tid >> 2;
    int fc = (tid & 3) * 4;                         // 0,4,8,12 within k-tile
    int fbase = (fc & 8) + ((fc & 4) ? 1 : 0);      // interleave [0,4,1,5,2,6,3,7]
    const float* ald0 = A + (size_t)(m0 + fr)*D_ + fc;
    const float* ald1 = A + (size_t)(m0 + fr + 64)*D_ + fc;
    const float* bld0 = W + (size_t)(n0 + fr)*D_ + fc;
    const float* bld1 = W + (size_t)(n0 + fr + 64)*D_ + fc;
    int sb0 = fr*GSTR + fbase, sb1 = (fr+64)*GSTR + fbase;

    float acc[4][4][4];
    #pragma unroll
    for (int mi = 0; mi < 4; mi++)
        #pragma unroll
        for (int ni = 0; ni < 4; ni++)
            #pragma unroll
            for (int e = 0; e < 4; e++) acc[mi][ni][e] = 0.f;

    // prologue: stage 0
    {
        float4 a0 = *(const float4*)(ald0);
        float4 a1 = *(const float4*)(ald1);
        float4 b0 = *(const float4*)(bld0);
        float4 b1 = *(const float4*)(bld1);
        As[0][sb0]=f2tf(a0.x); As[0][sb0+2]=f2tf(a0.y); As[0][sb0+4]=f2tf(a0.z); As[0][sb0+6]=f2tf(a0.w);
        As[0][sb1]=f2tf(a1.x); As[0][sb1+2]=f2tf(a1.y); As[0][sb1+4]=f2tf(a1.z); As[0][sb1+6]=f2tf(a1.w);
        Bs[0][sb0]=f2tf(b0.x); Bs[0][sb0+2]=f2tf(b0.y); Bs[0][sb0+4]=f2tf(b0.z); Bs[0][sb0+6]=f2tf(b0.w);
        Bs[0][sb1]=f2tf(b1.x); Bs[0][sb1+2]=f2tf(b1.y); Bs[0][sb1+4]=f2tf(b1.z); Bs[0][sb1+6]=f2tf(b1.w);
    }
    __syncthreads();

    const int NK = D_ / 16;   // 64 K-steps
    for (int kb = 0; kb < NK; kb++) {
        int cur = kb & 1, nxt = cur ^ 1;

        float4 a0, a1, b0, b1;
        if (kb + 1 < NK) {
            int ko = (kb + 1) * 16;
            a0 = *(const float4*)(ald0 + ko);
            a1 = *(const float4*)(ald1 + ko);
            b0 = *(const float4*)(bld0 + ko);
            b1 = *(const float4*)(bld1 + ko);
        }

        #pragma unroll
        for (int kblk = 0; kblk < 2; kblk++) {
            int kofs = kblk*8 + 2*tg;
            unsigned int af[4][4], bf[4][2];
            #pragma unroll
            for (int mi = 0; mi < 4; mi++) {
                int r = wrow*64 + mi*16 + g;
                float2 x0 = *(const float2*)&As[cur][ r     *GSTR + kofs];
                float2 x1 = *(const float2*)&As[cur][(r + 8)*GSTR + kofs];
                af[mi][0] = __float_as_uint(x0.x);
                af[mi][1] = __float_as_uint(x1.x);
                af[mi][2] = __float_as_uint(x0.y);
                af[mi][3] = __float_as_uint(x1.y);
            }
            #pragma unroll
            for (int ni = 0; ni < 4; ni++) {
                int c = wcol*32 + ni*8 + g;
                float2 bv = *(const float2*)&Bs[cur][c*GSTR + kofs];
                bf[ni][0] = __float_as_uint(bv.x);
                bf[ni][1] = __float_as_uint(bv.y);
            }
            #pragma unroll
            for (int mi = 0; mi < 4; mi++)
                #pragma unroll
                for (int ni = 0; ni < 4; ni++)
                    mma8(acc[mi][ni], af[mi], bf[ni]);
        }

        if (kb + 1 < NK) {
            As[nxt][sb0]=f2tf(a0.x); As[nxt][sb0+2]=f2tf(a0.y); As[nxt][sb0+4]=f2tf(a0.z); As[nxt][sb0+6]=f2tf(a0.w);
            As[nxt][sb1]=f2tf(a1.x); As[nxt][sb1+2]=f2tf(a1.y); As[nxt][sb1+4]=f2tf(a1.z); As[nxt][sb1+6]=f2tf(a1.w);
            Bs[nxt][sb0]=f2tf(b0.x); Bs[nxt][sb0+2]=f2tf(b0.y); Bs[nxt][sb0+4]=f2tf(b0.z); Bs[nxt][sb0+6]=f2tf(b0.w);
            Bs[nxt][sb1]=f2tf(b1.x); Bs[nxt][sb1+2]=f2tf(b1.y); Bs[nxt][sb1+4]=f2tf(b1.z); Bs[nxt][sb1+6]=f2tf(b1.w);
            __syncthreads();
        }
    }

    #pragma unroll
    for (int mi = 0; mi < 4; mi++) {
        #pragma unroll
        for (int ni = 0; ni < 4; ni++) {
            int r = m0 + wrow*64 + mi*16 + g;
            int c = n0 + wcol*32 + ni*8 + 2*tg;
            store_pair(mode, out, cosT, sinT, r,     c, acc[mi][ni][0], acc[mi][ni][1]);
            store_pair(mode, out, cosT, sinT, r + 8, c, acc[mi][ni][2], acc[mi][ni][3]);
        }
    }
}

// ---------------------------------------------------------------------------
// Flash attention: 1 block = 128 q-rows of one (b,h), 8 warps x 16 rows.
// Q fragments in registers (pre-scaled by 1/64). K and V^T in smem with
// pair-interleaved columns so every b-fragment is one conflict-free LDS.64.
// P is re-fragmented via warp shuffles (no smem round trip).
// ---------------------------------------------------------------------------
#define KSTR 72   // smem row stride (floats): conflict-free interleaved LDS.64

__global__ void __launch_bounds__(256, 2)
attn_kernel()
{
    __shared__ float Ks[64 * KSTR];
    __shared__ float Vt[64 * KSTR];

    int qt = blockIdx.x;          // 0..15  (128-row q tile)
    int bh = blockIdx.y;          // 0..31
    int b = bh >> 4, h = bh & 15;
    int tid = threadIdx.x, lane = tid & 31, w = tid >> 5;
    int g = lane >> 2, tg = lane & 3;

    const float* qp = g_q + (size_t)bh * S_ * DK_;
    const float* kp = g_k + (size_t)bh * S_ * DK_;
    const float* vp = g_v + (size_t)bh * S_ * DK_;

    int rowA = qt*128 + w*16 + g;   // global q row (lane's row A)
    int rowB = rowA + 8;
    int rowmax = qt*128 + w*16 + 15;

    // Q fragments, pre-scaled by 1/64 (folds the double 1/sqrt(dk))
    unsigned int aq[8][4];
    #pragma unroll
    for (int ks = 0; ks < 8; ks++) {
        int k8 = ks * 8;
        aq[ks][0] = __float_as_uint(f2tf(qp[(size_t)rowA*DK_ + k8+tg  ] * 0.015625f));
        aq[ks][1] = __float_as_uint(f2tf(qp[(size_t)rowB*DK_ + k8+tg  ] * 0.015625f));
        aq[ks][2] = __float_as_uint(f2tf(qp[(size_t)rowA*DK_ + k8+tg+4] * 0.015625f));
        aq[ks][3] = __float_as_uint(f2tf(qp[(size_t)rowB*DK_ + k8+tg+4] * 0.015625f));
    }

    float oacc[8][4];
    #pragma unroll
    for (int ni = 0; ni < 8; ni++)
        #pragma unroll
        for (int e = 0; e < 4; e++) oacc[ni][e] = 0.f;

    float mA = -1e30f, mB = -1e30f, lA = 0.f, lB = 0.f;

    int ntiles = 2*qt + 2;
    for (int kt = 0; kt < ntiles; kt++) {
        int kb = kt * 64;
        __syncthreads();
        // K fill: row-major, columns pair-interleaved [0,4,1,5,2,6,3,7] per 8-group
        #pragma unroll
        for (int it = 0; it < 4; it++) {
            int idx = tid + it*256;
            int r = idx >> 4, c = (idx & 15) * 4;
            float4 v4 = *(const float4*)(kp + (size_t)(kb + r)*DK_ + c);
            int base = r*KSTR + (c & ~7) + ((c & 4) ? 1 : 0);
            Ks[base    ] = f2tf(v4.x);
            Ks[base + 2] = f2tf(v4.y);
            Ks[base + 4] = f2tf(v4.z);
            Ks[base + 6] = f2tf(v4.w);
        }
        // V fill transposed: Vt[dk][perm(key)], same pair interleave on key index
        #pragma unroll
        for (int it = 0; it < 4; it++) {
            int idx = tid + it*256;
            int r = idx & 63, c = (idx >> 6) * 4;
            float4 v4 = *(const float4*)(vp + (size_t)(kb + r)*DK_ + c);
            int pr = (r & ~7) + ((r & 3)*2) + ((r >> 2) & 1);
            Vt[(c    )*KSTR + pr] = f2tf(v4.x);
            Vt[(c + 1)*KSTR + pr] = f2tf(v4.y);
            Vt[(c + 2)*KSTR + pr] = f2tf(v4.z);
            Vt[(c + 3)*KSTR + pr] = f2tf(v4.w);
        }
        __syncthreads();

        if (kb > rowmax) continue;   // fully masked for this warp

        // S = (Q/64) K^T  : warp computes 16 x 64
        float sacc[8][4];
        #pragma unroll
        for (int ni = 0; ni < 8; ni++)
            #pragma unroll
            for (int e = 0; e < 4; e++) sacc[ni][e] = 0.f;

        #pragma unroll
        for (int ks = 0; ks < 8; ks++) {
            #pragma unroll
            for (int ni = 0; ni < 8; ni++) {
                float2 bv = *(const float2*)(&Ks[(ni*8 + g)*KSTR + ks*8 + 2*tg]);
                unsigned int bf[2] = { __float_as_uint(bv.x), __float_as_uint(bv.y) };
                mma8(sacc[ni], aq[ks], bf);
            }
        }

        // causal mask + running row max
        float tmA = -1e30f, tmB = -1e30f;
        #pragma unroll
        for (int ni = 0; ni < 8; ni++) {
            int c0 = kb + ni*8 + 2*tg;
            float v0 = sacc[ni][0], v1 = sacc[ni][1];
            float v2 = sacc[ni][2], v3 = sacc[ni][3];
            if (c0     > rowA) v0 = -1e9f;
            if (c0 + 1 > rowA) v1 = -1e9f;
            if (c0     > rowB) v2 = -1e9f;
            if (c0 + 1 > rowB) v3 = -1e9f;
            sacc[ni][0] = v0; sacc[ni][1] = v1;
            sacc[ni][2] = v2; sacc[ni][3] = v3;
            tmA = fmaxf(tmA, fmaxf(v0, v1));
            tmB = fmaxf(tmB, fmaxf(v2, v3));
        }
        tmA = fmaxf(tmA, __shfl_xor_sync(0xffffffffu, tmA, 1));
        tmA = fmaxf(tmA, __shfl_xor_sync(0xffffffffu, tmA, 2));
        tmB = fmaxf(tmB, __shfl_xor_sync(0xffffffffu, tmB, 1));
        tmB = fmaxf(tmB, __shfl_xor_sync(0xffffffffu, tmB, 2));

        float mAn = fmaxf(mA, tmA), mBn = fmaxf(mB, tmB);
        float alA = __expf(mA - mAn), alB = __expf(mB - mBn);

        float sumA = 0.f, sumB = 0.f;
        #pragma unroll
        for (int ni = 0; ni < 8; ni++) {
            float p0 = __expf(sacc[ni][0] - mAn);
            float p1 = __expf(sacc[ni][1] - mAn);
            float p2 = __expf(sacc[ni][2] - mBn);
            float p3 = __expf(sacc[ni][3] - mBn);
            sumA += p0 + p1;
            sumB += p2 + p3;
            sacc[ni][0] = f2tf(p0); sacc[ni][1] = f2tf(p1);
            sacc[ni][2] = f2tf(p2); sacc[ni][3] = f2tf(p3);
        }
        sumA += __shfl_xor_sync(0xffffffffu, sumA, 1);
        sumA += __shfl_xor_sync(0xffffffffu, sumA, 2);
        sumB += __shfl_xor_sync(0xffffffffu, sumB, 1);
        sumB += __shfl_xor_sync(0xffffffffu, sumB, 2);

        lA = lA * alA + sumA;
        lB = lB * alB + sumB;
        mA = mAn; mB = mBn;

        #pragma unroll
        for (int ni = 0; ni < 8; ni++) {
            oacc[ni][0] *= alA; oacc[ni][1] *= alA;
            oacc[ni][2] *= alB; oacc[ni][3] *= alB;
        }

        // O += P V : P a-fragments built from c-fragments via shuffles
        int srcA = (lane & ~3) | (tg >> 1);
        int srcB = srcA + 2;
        bool odd = (tg & 1);
        #pragma unroll
        for (int ks = 0; ks < 8; ks++) {
            float x0 = __shfl_sync(0xffffffffu, sacc[ks][0], srcA);
            float y0 = __shfl_sync(0xffffffffu, sacc[ks][1], srcA);
            float x1 = __shfl_sync(0xffffffffu, sacc[ks][2], srcA);
            float y1 = __shfl_sync(0xffffffffu, sacc[ks][3], srcA);
            float x2 = __shfl_sync(0xffffffffu, sacc[ks][0], srcB);
            float y2 = __shfl_sync(0xffffffffu, sacc[ks][1], srcB);
            float x3 = __shfl_sync(0xffffffffu, sacc[ks][2], srcB);
            float y3 = __shfl_sync(0xffffffffu, sacc[ks][3], srcB);
            unsigned int af[4];
            af[0] = __float_as_uint(odd ? y0 : x0);
            af[1] = __float_as_uint(odd ? y1 : x1);
            af[2] = __float_as_uint(odd ? y2 : x2);
            af[3] = __float_as_uint(odd ? y3 : x3);
            #pragma unroll
            for (int ni = 0; ni < 8; ni++) {
                float2 bv = *(const float2*)(&Vt[(ni*8 + g)*KSTR + ks*8 + 2*tg]);
                unsigned int bf[2] = { __float_as_uint(bv.x), __float_as_uint(bv.y) };
                mma8(oacc[ni], af, bf);
            }
        }
    }

    float invA = 1.f / lA, invB = 1.f / lB;
    float* aoA = g_ao + ((size_t)b*S_ + rowA)*D_ + h*DK_;
    float* aoB = aoA + (size_t)8*D_;
    #pragma unroll
    for (int ni = 0; ni < 8; ni++) {
        int c = ni*8 + 2*tg;
        *(float2*)(aoA + c) = make_float2(oacc[ni][0]*invA, oacc[ni][1]*invA);
        *(float2*)(aoB + c) = make_float2(oacc[ni][2]*invB, oacc[ni][3]*invB);
    }
}

// ---------------------------------------------------------------------------

extern "C" void kernel_launch(void* const* d_in, const int* in_sizes, int n_in,
                              void* d_out, int out_size)
{
    const float* x  = (const float*)d_in[0];
    const float* fc = (const float*)d_in[1];
    const float* fs = (const float*)d_in[2];
    // d_in[3] is the additive mask; causality is applied analytically.
    const float* wq = (const float*)d_in[4];
    const float* wk = (const float*)d_in[5];
    const float* wv = (const float*)d_in[6];
    const float* wo = (const float*)d_in[7];
    float* out = (float*)d_out;

    float *qb, *kb, *vb, *ab;
    cudaGetSymbolAddress((void**)&qb, g_q);
    cudaGetSymbolAddress((void**)&kb, g_k);
    cudaGetSymbolAddress((void**)&vb, g_v);
    cudaGetSymbolAddress((void**)&ab, g_ao);

    // Fused QKV projections (+RoPE on Q,K) in one launch
    gemm_kernel<<<dim3(D_/128, M_/128, 3), 256>>>(x, wq, wk, wv, qb, kb, vb, fc, fs, 1);

    attn_kernel<<<dim3(S_/128, B_*H_), 256>>>();

    // Output projection
    gemm_kernel<<<dim3(D_/128, M_/128, 1), 256>>>(ab, wo, 0, 0, out, 0, 0, fc, fs, 0);
}